// round 4
// baseline (speedup 1.0000x reference)
#include <cuda_runtime.h>

// Problem constants
#define BB   4
#define CC   16
#define HH   64
#define WW   64
#define FF   32
#define K2   9
#define NCOEF 10          // 6 num + 4 denom per (f,c,k)
#define TILE_W 32
#define THREADS 128       // 4 warps, each warp -> 8 pixels (4 pixel-pairs)

typedef unsigned long long u64;

// Scratch: coefficients transposed AND duplicated for f32x2 math.
// Layout: [c][k][f][10] float2, each float2 = {v, v}.
__device__ float2 g_coefP[CC * K2 * FF * NCOEF];   // 46080 float2 = 368 KB

// ---------------------------------------------------------------------------
// packed f32x2 helpers (sm_103a)
// ---------------------------------------------------------------------------
__device__ __forceinline__ u64 fma2(u64 a, u64 b, u64 c) {
    u64 d; asm("fma.rn.f32x2 %0, %1, %2, %3;" : "=l"(d) : "l"(a), "l"(b), "l"(c)); return d;
}
__device__ __forceinline__ u64 mul2(u64 a, u64 b) {
    u64 d; asm("mul.rn.f32x2 %0, %1, %2;" : "=l"(d) : "l"(a), "l"(b)); return d;
}
__device__ __forceinline__ u64 add2(u64 a, u64 b) {
    u64 d; asm("add.rn.f32x2 %0, %1, %2;" : "=l"(d) : "l"(a), "l"(b)); return d;
}
__device__ __forceinline__ u64 abs2(u64 a) {
    u64 d; asm("and.b64 %0, %1, %2;" : "=l"(d) : "l"(a), "l"(0x7FFFFFFF7FFFFFFFULL)); return d;
}
__device__ __forceinline__ void unpack2(u64 v, float& lo, float& hi) {
    asm("mov.b64 {%0, %1}, %2;" : "=f"(lo), "=f"(hi) : "l"(v));
}
__device__ __forceinline__ float rcp_fast(float q) {
    float r; asm("rcp.approx.f32 %0, %1;" : "=f"(r) : "f"(q)); return r;
}

// ---------------------------------------------------------------------------
// Kernel 1: transpose + duplicate coefficients into [c][k][f][n] float2 {v,v}
// ---------------------------------------------------------------------------
__global__ void transpose_coefs_kernel(const float* __restrict__ nums,
                                       const float* __restrict__ denoms) {
    int idx = blockIdx.x * blockDim.x + threadIdx.x;
    const int total = CC * K2 * FF * NCOEF;
    if (idx >= total) return;
    int n = idx % NCOEF;
    int f = (idx / NCOEF) % FF;
    int k = (idx / (NCOEF * FF)) % K2;
    int c = idx / (NCOEF * FF * K2);
    float v;
    if (n < 6) v = nums  [(((f * CC + c) * K2) + k) * 6 + n];
    else       v = denoms[(((f * CC + c) * K2) + k) * 4 + (n - 6)];
    g_coefP[idx] = make_float2(v, v);
}

// ---------------------------------------------------------------------------
// Kernel 2: rational (Pade) conv with packed f32x2 math.
//   grid  = (W/TILE_W, H, B) = (2, 64, 4) = 512 blocks
//   block = 128 threads = 4 warps
//   lane  = output channel f; warp -> 8 consecutive output pixels
// ---------------------------------------------------------------------------
__global__ __launch_bounds__(THREADS)
void rational_conv_kernel(const float* __restrict__ x, float* __restrict__ out) {
    // x pairs: xsp[c][r][s] = {x(col s-1+wbase), x(col s+wbase)}, s = 0..32
    __shared__ float2 xsp[CC][3][33];
    // coeffs for current c: [k][f][5] ulonglong2 (= 10 duplicated pairs)
    __shared__ __align__(16) float cs[K2 * FF * NCOEF * 2];

    const int wbase = blockIdx.x * TILE_W;
    const int h     = blockIdx.y;
    const int b     = blockIdx.z;
    const int tid   = threadIdx.x;
    const int lane  = tid & 31;        // f
    const int warp  = tid >> 5;        // 0..3
    const int px0   = warp * 8;        // pixel offset inside tile

    // --- Build paired input halo tile (zero-padded)
    const int XSP_N = CC * 3 * 33;
    for (int i = tid; i < XSP_N; i += THREADS) {
        int s = i % 33;
        int r = (i / 33) % 3;
        int c = i / 99;
        int hh = h - 1 + r;
        int c0 = wbase - 1 + s;     // left col of the pair
        float v0 = 0.0f, v1 = 0.0f;
        if (hh >= 0 && hh < HH) {
            const float* row = x + ((b * CC + c) * HH + hh) * WW;
            if (c0 >= 0 && c0 < WW) v0 = row[c0];
            if (c0 + 1 < WW)        v1 = row[c0 + 1];   // c0+1 >= 0 always
        }
        xsp[c][r][s] = make_float2(v0, v1);
    }

    const u64 ONE2 = 0x3F8000003F800000ULL;  // {1.0f, 1.0f}

    float acc[8];
    #pragma unroll
    for (int i = 0; i < 8; ++i) acc[i] = 0.0f;

    const u64* xsp_u = reinterpret_cast<const u64*>(&xsp[0][0][0]);
    const ulonglong2* cs_u2 = reinterpret_cast<const ulonglong2*>(cs);

    for (int c = 0; c < CC; ++c) {
        __syncthreads();   // protect previous reads (and xsp build on iter 0)
        // --- stage this channel's coeffs (coalesced float4 copy, 23040 B)
        {
            const float4* src = reinterpret_cast<const float4*>(
                g_coefP + c * (K2 * FF * NCOEF));
            float4* dst = reinterpret_cast<float4*>(cs);
            const int NV = K2 * FF * NCOEF * 2 / 4;   // 1440
            #pragma unroll
            for (int i = tid; i < NV; i += THREADS)
                dst[i] = src[i];
        }
        __syncthreads();

        #pragma unroll
        for (int k = 0; k < K2; ++k) {
            const int a  = k / 3;
            const int bb = k % 3;
            // 5 conflict-free LDS.128: lane stride = 80B = 20 banks
            const ulonglong2* cl = cs_u2 + (k * FF + lane) * 5;
            ulonglong2 u0 = cl[0];   // {n0n0, n1n1}
            ulonglong2 u1 = cl[1];   // {n2n2, n3n3}
            ulonglong2 u2 = cl[2];   // {n4n4, n5n5}
            ulonglong2 u3 = cl[3];   // {d0d0, d1d1}
            ulonglong2 u4 = cl[4];   // {d2d2, d3d3}

            const u64* xrow = xsp_u + (c * 3 + a) * 33;

            #pragma unroll
            for (int p = 0; p < 4; ++p) {
                const u64 xv = xrow[px0 + 2 * p + bb];   // warp-uniform LDS.64
                // P(x): Horner, 5 x FFMA2
                u64 pp = fma2(xv, u2.y, u2.x);   // n5*x + n4
                pp = fma2(xv, pp, u1.y);
                pp = fma2(xv, pp, u1.x);
                pp = fma2(xv, pp, u0.y);
                pp = fma2(xv, pp, u0.x);
                // S(x) = x*(d0 + d1 x + d2 x^2 + d3 x^3)
                u64 sp = fma2(xv, u4.y, u4.x);
                sp = fma2(xv, sp, u3.y);
                sp = fma2(xv, sp, u3.x);
                sp = mul2(sp, xv);
                // Q = 1 + |S|
                u64 qp = add2(abs2(sp), ONE2);
                float q0, q1, p0, p1;
                unpack2(qp, q0, q1);
                unpack2(pp, p0, p1);
                const float r0 = rcp_fast(q0);
                const float r1 = rcp_fast(q1);
                acc[2 * p]     = fmaf(p0, r0, acc[2 * p]);
                acc[2 * p + 1] = fmaf(p1, r1, acc[2 * p + 1]);
            }
        }
    }

    // --- write 8 consecutive pixels: 2 x STG.128
    float* op = &out[((b * FF + lane) * HH + h) * WW + wbase + px0];
    *reinterpret_cast<float4*>(op)     = make_float4(acc[0], acc[1], acc[2], acc[3]);
    *reinterpret_cast<float4*>(op + 4) = make_float4(acc[4], acc[5], acc[6], acc[7]);
}

// ---------------------------------------------------------------------------
// Launch
// ---------------------------------------------------------------------------
extern "C" void kernel_launch(void* const* d_in, const int* in_sizes, int n_in,
                              void* d_out, int out_size) {
    const float* x      = (const float*)d_in[0];   // (4,16,64,64)
    const float* nums   = (const float*)d_in[1];   // (32,16,3,3,6)
    const float* denoms = (const float*)d_in[2];   // (32,16,3,3,4)
    float* out = (float*)d_out;                    // (4,32,64,64)

    const int total_coef = CC * K2 * FF * NCOEF;
    transpose_coefs_kernel<<<(total_coef + 255) / 256, 256>>>(nums, denoms);

    dim3 grid(WW / TILE_W, HH, BB);
    rational_conv_kernel<<<grid, THREADS>>>(x, out);
}